// round 3
// baseline (speedup 1.0000x reference)
#include <cuda_runtime.h>
#include <math.h>

#define NN 100000
#define EE 1600000

// ---------------- scratch (static device globals; no allocation) ----------------
__device__ int   g_is64;
__device__ int   g_src[EE];
__device__ int   g_dst[EE];
__device__ int   g_cnt[NN];
__device__ int   g_rowptr[NN + 1];
__device__ int   g_fill[NN];
__device__ int   g_colidx[EE];
__device__ int   g_bsum[128];
__device__ int   g_boff[128];
__device__ float g_dinv[NN];
__device__ float g_y[(size_t)NN * 128];
__device__ float g_hA[(size_t)NN * 128];
__device__ float g_hB[(size_t)NN * 128];

// ---------------- edge-index format detection + conversion ----------------
// If edge_index is int64 (little-endian, values < 2^31), every odd 32-bit word
// of the first 256 pairs is 0. With int32 data those words are random node ids;
// P(all 256 == 0) ~ (1e-5)^256 == never.
__global__ void k_detect(const int* __restrict__ u) {
    __shared__ int any;
    if (threadIdx.x == 0) any = 0;
    __syncthreads();
    if (u[2 * threadIdx.x + 1] != 0) atomicOr(&any, 1);
    __syncthreads();
    if (threadIdx.x == 0) g_is64 = any ? 0 : 1;
}

__global__ void k_convert(const int* __restrict__ u) {
    int i = blockIdx.x * blockDim.x + threadIdx.x;
    if (i >= EE) return;
    if (g_is64) {
        g_src[i] = u[2 * i];
        g_dst[i] = u[2 * EE + 2 * i];
    } else {
        g_src[i] = u[i];
        g_dst[i] = u[EE + i];
    }
}

// ---------------- degree / CSR build ----------------
__global__ void k_zero_cnt() {
    int i = blockIdx.x * blockDim.x + threadIdx.x;
    if (i < NN) g_cnt[i] = 0;
}

__global__ void k_hist() {
    int i = blockIdx.x * blockDim.x + threadIdx.x;
    if (i < EE) atomicAdd(&g_cnt[g_dst[i]], 1);
}

__global__ void k_dinv() {
    int i = blockIdx.x * blockDim.x + threadIdx.x;
    if (i < NN) g_dinv[i] = rsqrtf((float)g_cnt[i] + 1.0f);
}

__device__ __forceinline__ int block_scan_incl(int v) {
    __shared__ int ws[32];
    int lane = threadIdx.x & 31;
    int w = threadIdx.x >> 5;
#pragma unroll
    for (int o = 1; o < 32; o <<= 1) {
        int n = __shfl_up_sync(0xffffffffu, v, o);
        if (lane >= o) v += n;
    }
    if (lane == 31) ws[w] = v;
    __syncthreads();
    if (w == 0) {
        int s = ws[lane];
#pragma unroll
        for (int o = 1; o < 32; o <<= 1) {
            int n = __shfl_up_sync(0xffffffffu, s, o);
            if (lane >= o) s += n;
        }
        ws[lane] = s;
    }
    __syncthreads();
    if (w > 0) v += ws[w - 1];
    return v;
}

__global__ void k_scan_a() {  // 1024 threads/block
    int i = blockIdx.x * 1024 + threadIdx.x;
    int c = (i < NN) ? g_cnt[i] : 0;
    int s = block_scan_incl(c);
    if (i < NN) g_rowptr[i + 1] = s;
    if (threadIdx.x == 1023) g_bsum[blockIdx.x] = s;
}

__global__ void k_scan_b(int nblk) {  // 1 block, 1024 threads
    int v = (threadIdx.x < nblk) ? g_bsum[threadIdx.x] : 0;
    int s = block_scan_incl(v);
    if (threadIdx.x < nblk) g_boff[threadIdx.x] = s - v;  // exclusive
}

__global__ void k_scan_c() {
    int i = blockIdx.x * 1024 + threadIdx.x;
    if (i < NN) g_rowptr[i + 1] += g_boff[blockIdx.x];
}

__global__ void k_fill_init() {
    int i = blockIdx.x * blockDim.x + threadIdx.x;
    if (i == 0) { g_rowptr[0] = 0; g_fill[0] = 0; }
    else if (i < NN) g_fill[i] = g_rowptr[i];
}

__global__ void k_scatter() {
    int i = blockIdx.x * blockDim.x + threadIdx.x;
    if (i < EE) {
        int d = g_dst[i];
        int p = atomicAdd(&g_fill[d], 1);
        g_colidx[p] = g_src[i];
    }
}

// ---------------- GEMM: Y[n][j] = dinv[n] * sum_k H[n][k] W[k][j] ----------------
template <int FIN, int FOUT>
__global__ void __launch_bounds__(128) k_gemm(const float* __restrict__ H,
                                              const float* __restrict__ W,
                                              float* __restrict__ Y) {
    constexpr int BN = 64, KB = 32, TN = FOUT / 16, TM = 8;
    __shared__ float Ws[FIN * FOUT];
    __shared__ float Xs[KB][BN + 4];
    int tid = threadIdx.x;
    for (int i = tid; i < FIN * FOUT; i += 128) Ws[i] = W[i];
    int nb = blockIdx.x * BN;
    float acc[TM][TN];
#pragma unroll
    for (int i = 0; i < TM; i++)
#pragma unroll
        for (int j = 0; j < TN; j++) acc[i][j] = 0.f;
    int tx = tid & 15, ty = tid >> 4;
    int n0 = ty * TM, j0 = tx * TN;
    for (int kb = 0; kb < FIN; kb += KB) {
        __syncthreads();
        for (int idx = tid; idx < KB * BN; idx += 128) {
            int n = idx >> 5, k = idx & 31;
            int gn = nb + n;
            Xs[k][n] = (gn < NN) ? H[(size_t)gn * FIN + kb + k] : 0.f;
        }
        __syncthreads();
#pragma unroll
        for (int k = 0; k < KB; k++) {
            float xv[TM];
            float4 xa = *(const float4*)&Xs[k][n0];
            float4 xb = *(const float4*)&Xs[k][n0 + 4];
            xv[0] = xa.x; xv[1] = xa.y; xv[2] = xa.z; xv[3] = xa.w;
            xv[4] = xb.x; xv[5] = xb.y; xv[6] = xb.z; xv[7] = xb.w;
            float wv[TN];
            const float* wr = &Ws[(kb + k) * FOUT + j0];
#pragma unroll
            for (int j = 0; j < TN; j += 4) {
                float4 w4 = *(const float4*)&wr[j];
                wv[j] = w4.x; wv[j + 1] = w4.y; wv[j + 2] = w4.z; wv[j + 3] = w4.w;
            }
#pragma unroll
            for (int i = 0; i < TM; i++)
#pragma unroll
                for (int j = 0; j < TN; j++) acc[i][j] = fmaf(xv[i], wv[j], acc[i][j]);
        }
    }
#pragma unroll
    for (int i = 0; i < TM; i++) {
        int gn = nb + n0 + i;
        if (gn < NN) {
            float dv = g_dinv[gn];
            float* yr = Y + (size_t)gn * FOUT + j0;
#pragma unroll
            for (int j = 0; j < TN; j += 4) {
                float4 o;
                o.x = acc[i][j] * dv; o.y = acc[i][j + 1] * dv;
                o.z = acc[i][j + 2] * dv; o.w = acc[i][j + 3] * dv;
                *(float4*)&yr[j] = o;
            }
        }
    }
}

// ---------------- aggregation + bias + LayerNorm + ELU (warp per node) ----------------
template <int F>
__global__ void __launch_bounds__(256) k_agg(const float* __restrict__ Y,
                                             const float* __restrict__ bias,
                                             const float* __restrict__ gam,
                                             const float* __restrict__ bet,
                                             float* __restrict__ O) {
    constexpr int VPL = F / 32;
    int wid = threadIdx.x >> 5;
    int lane = threadIdx.x & 31;
    int node = blockIdx.x * 8 + wid;
    if (node >= NN) return;
    int fi = lane * VPL;
    const float* yself = Y + (size_t)node * F + fi;
    float acc[VPL];
    if constexpr (VPL == 2) {
        float2 t = *(const float2*)yself; acc[0] = t.x; acc[1] = t.y;
    } else {
        float4 t = *(const float4*)yself;
        acc[0] = t.x; acc[1] = t.y; acc[2] = t.z; acc[3] = t.w;
    }
    int e = g_rowptr[node];
    int end = g_rowptr[node + 1];
    for (; e + 2 <= end; e += 2) {
        int s0 = __ldg(&g_colidx[e]);
        int s1 = __ldg(&g_colidx[e + 1]);
        const float* r0 = Y + (size_t)s0 * F + fi;
        const float* r1 = Y + (size_t)s1 * F + fi;
        if constexpr (VPL == 2) {
            float2 a = *(const float2*)r0;
            float2 b = *(const float2*)r1;
            acc[0] += a.x + b.x; acc[1] += a.y + b.y;
        } else {
            float4 a = *(const float4*)r0;
            float4 b = *(const float4*)r1;
            acc[0] += a.x + b.x; acc[1] += a.y + b.y;
            acc[2] += a.z + b.z; acc[3] += a.w + b.w;
        }
    }
    if (e < end) {
        int s0 = __ldg(&g_colidx[e]);
        const float* r0 = Y + (size_t)s0 * F + fi;
        if constexpr (VPL == 2) {
            float2 a = *(const float2*)r0; acc[0] += a.x; acc[1] += a.y;
        } else {
            float4 a = *(const float4*)r0;
            acc[0] += a.x; acc[1] += a.y; acc[2] += a.z; acc[3] += a.w;
        }
    }
    float dv = g_dinv[node];
    float t[VPL];
    float s1 = 0.f;
#pragma unroll
    for (int v = 0; v < VPL; v++) { t[v] = acc[v] * dv + bias[fi + v]; s1 += t[v]; }
#pragma unroll
    for (int o = 16; o > 0; o >>= 1) s1 += __shfl_xor_sync(0xffffffffu, s1, o);
    float mu = s1 * (1.0f / F);
    float s2 = 0.f;
#pragma unroll
    for (int v = 0; v < VPL; v++) { float d = t[v] - mu; s2 += d * d; }
#pragma unroll
    for (int o = 16; o > 0; o >>= 1) s2 += __shfl_xor_sync(0xffffffffu, s2, o);
    float rs = rsqrtf(s2 * (1.0f / F) + 1e-5f);
    float ov[VPL];
#pragma unroll
    for (int v = 0; v < VPL; v++) {
        float z = (t[v] - mu) * rs * gam[fi + v] + bet[fi + v];
        ov[v] = (z > 0.f) ? z : expm1f(z);
    }
    float* orow = O + (size_t)node * F + fi;
    if constexpr (VPL == 2) {
        *(float2*)orow = make_float2(ov[0], ov[1]);
    } else {
        *(float4*)orow = make_float4(ov[0], ov[1], ov[2], ov[3]);
    }
}

// ---------------- head: (h@lw1+lb1) -> LN -> ELU -> @lw2+lb2 ----------------
__global__ void __launch_bounds__(256) k_head(const float* __restrict__ H,
                                              const float* __restrict__ lw1,
                                              const float* __restrict__ lb1,
                                              const float* __restrict__ g4,
                                              const float* __restrict__ be4,
                                              const float* __restrict__ lw2,
                                              const float* __restrict__ lb2,
                                              float* __restrict__ out) {
    __shared__ float W1s[64 * 32];
    __shared__ float W2s[32 * 32];
    __shared__ float hs[8][64];
    int tid = threadIdx.x;
    for (int i = tid; i < 64 * 32; i += 256) W1s[i] = lw1[i];
    for (int i = tid; i < 32 * 32; i += 256) W2s[i] = lw2[i];
    int wid = tid >> 5, lane = tid & 31;
    int node = blockIdx.x * 8 + wid;
    __syncthreads();
    if (node >= NN) return;
    const float* hr = H + (size_t)node * 64;
    hs[wid][lane] = hr[lane];
    hs[wid][lane + 32] = hr[lane + 32];
    __syncwarp();
    float u = lb1[lane];
#pragma unroll
    for (int k = 0; k < 64; k++) u = fmaf(hs[wid][k], W1s[k * 32 + lane], u);
    // LN over 32 features (one per lane)
    float s = u;
#pragma unroll
    for (int o = 16; o > 0; o >>= 1) s += __shfl_xor_sync(0xffffffffu, s, o);
    float mu = s * (1.0f / 32.0f);
    float d = u - mu;
    float s2 = d * d;
#pragma unroll
    for (int o = 16; o > 0; o >>= 1) s2 += __shfl_xor_sync(0xffffffffu, s2, o);
    float rs = rsqrtf(s2 * (1.0f / 32.0f) + 1e-5f);
    float v = d * rs * g4[lane] + be4[lane];
    v = (v > 0.f) ? v : expm1f(v);
    float o2 = lb2[lane];
#pragma unroll
    for (int k = 0; k < 32; k++) {
        float vk = __shfl_sync(0xffffffffu, v, k);
        o2 = fmaf(vk, W2s[k * 32 + lane], o2);
    }
    out[(size_t)node * 32 + lane] = o2;
}

// ---------------- launch ----------------
extern "C" void kernel_launch(void* const* d_in, const int* in_sizes, int n_in,
                              void* d_out, int out_size) {
    const float* x   = (const float*)d_in[0];
    const int*   ei  = (const int*)d_in[1];
    const float* W1  = (const float*)d_in[2];
    const float* b1  = (const float*)d_in[3];
    const float* g1  = (const float*)d_in[4];
    const float* be1 = (const float*)d_in[5];
    const float* W2  = (const float*)d_in[6];
    const float* b2  = (const float*)d_in[7];
    const float* g2  = (const float*)d_in[8];
    const float* be2 = (const float*)d_in[9];
    const float* W3  = (const float*)d_in[10];
    const float* b3  = (const float*)d_in[11];
    const float* g3  = (const float*)d_in[12];
    const float* be3 = (const float*)d_in[13];
    const float* lw1 = (const float*)d_in[14];
    const float* lb1 = (const float*)d_in[15];
    const float* g4  = (const float*)d_in[16];
    const float* be4 = (const float*)d_in[17];
    const float* lw2 = (const float*)d_in[18];
    const float* lb2 = (const float*)d_in[19];
    float* out = (float*)d_out;

    void *py, *pA, *pB;
    cudaGetSymbolAddress(&py, g_y);
    cudaGetSymbolAddress(&pA, g_hA);
    cudaGetSymbolAddress(&pB, g_hB);
    float* Y  = (float*)py;
    float* hA = (float*)pA;
    float* hB = (float*)pB;

    const int EB = (EE + 255) / 256;
    const int NBl = (NN + 255) / 256;
    const int NSC = (NN + 1023) / 1024;  // 98

    k_detect<<<1, 256>>>(ei);
    k_convert<<<EB, 256>>>(ei);
    k_zero_cnt<<<NBl, 256>>>();
    k_hist<<<EB, 256>>>();
    k_dinv<<<NBl, 256>>>();
    k_scan_a<<<NSC, 1024>>>();
    k_scan_b<<<1, 1024>>>(NSC);
    k_scan_c<<<NSC, 1024>>>();
    k_fill_init<<<NBl, 256>>>();
    k_scatter<<<EB, 256>>>();

    const int GB = (NN + 63) / 64;    // gemm blocks
    const int AB = (NN + 7) / 8;      // agg/head blocks

    k_gemm<128, 64><<<GB, 128>>>(x, W1, Y);
    k_agg<64><<<AB, 256>>>(Y, b1, g1, be1, hA);
    k_gemm<64, 128><<<GB, 128>>>(hA, W2, Y);
    k_agg<128><<<AB, 256>>>(Y, b2, g2, be2, hB);
    k_gemm<128, 64><<<GB, 128>>>(hB, W3, Y);
    k_agg<64><<<AB, 256>>>(Y, b3, g3, be3, hA);
    k_head<<<AB, 256>>>(hA, lw1, lb1, g4, be4, lw2, lb2, out);
}